// round 1
// baseline (speedup 1.0000x reference)
#include <cuda_runtime.h>
#include <cstdint>

#define NU 200000
#define NM 80000
#define NN 280000            // real nodes
#define NP 280064            // padded to 2188*128
#define H  64

// ---------------- scratch (device globals; no allocation allowed) ----------
__device__ float g_X0[(size_t)NP * H];   // node features layer-in / final out
__device__ float g_X1[(size_t)NP * H];   // layer-1 output
__device__ float g_AGG[(size_t)NP * H];  // scatter accumulator
__device__ float g_DEG[NP];
__device__ float g_INV[NP];
__device__ int   g_flag32[1];            // 1 => indices are int32, 0 => int64

// ---------------- index dtype detection ------------------------------------
__global__ void k_zero_flag() { g_flag32[0] = 0; }

__global__ void k_detect(const long long* __restrict__ ei, int ncheck) {
    int i = blockIdx.x * blockDim.x + threadIdx.x;
    if (i < ncheck) {
        long long v = ei[i];
        if (v < 0 || v >= (long long)NN) atomicOr(g_flag32, 1);
    }
}

__device__ __forceinline__ int get_idx(const void* ei, int pos, int f32) {
    if (f32) return ((const int*)ei)[pos];
    return (int)((const long long*)ei)[pos];
}

// ---------------- node init -------------------------------------------------
// x_movie = movie_x @ lin_W.T + lin_b + movie_emb   (users are memcpy'd)
__global__ void k_init_movie(const float* __restrict__ movie_x,
                             const float* __restrict__ lin_W,
                             const float* __restrict__ lin_b,
                             const float* __restrict__ movie_emb,
                             float* __restrict__ X0) {
    int t = blockIdx.x * blockDim.x + threadIdx.x;
    if (t >= NM * H) return;
    int m = t >> 6, j = t & 63;
    float acc = __ldg(&lin_b[j]);
#pragma unroll
    for (int k = 0; k < 20; ++k)
        acc += __ldg(&movie_x[m * 20 + k]) * __ldg(&lin_W[j * 20 + k]);
    X0[(size_t)(NU + m) * H + j] = acc + __ldg(&movie_emb[t]);
}

// ---------------- degree / inverse ------------------------------------------
__global__ void k_deg(const void* __restrict__ ei, int E) {
    int e = blockIdx.x * blockDim.x + threadIdx.x;
    if (e >= E) return;
    int f = g_flag32[0];
    int dst = get_idx(ei, E + e, f);
    atomicAdd(&g_DEG[dst], 1.0f);
}

__global__ void k_inv() {
    int i = blockIdx.x * blockDim.x + threadIdx.x;
    if (i < NP) g_INV[i] = 1.0f / fmaxf(g_DEG[i], 1.0f);
}

// ---------------- scatter: AGG[dst] += X[src] -------------------------------
// one thread per (edge, float4-chunk): 16 chunks cover H=64
__global__ void k_scatter(const float4* __restrict__ X,
                          const void* __restrict__ ei, int E) {
    int t = blockIdx.x * blockDim.x + threadIdx.x;
    if (t >= E * 16) return;
    int e = t >> 4, c = t & 15;
    int f = g_flag32[0];
    int src = get_idx(ei, e, f);
    int dst = get_idx(ei, E + e, f);
    float4 v = __ldg(&X[(size_t)src * 16 + c]);
    float* p = &g_AGG[(size_t)dst * H + c * 4];
    asm volatile("red.global.add.v4.f32 [%0], {%1,%2,%3,%4};"
                 :: "l"(p), "f"(v.x), "f"(v.y), "f"(v.z), "f"(v.w)
                 : "memory");
}

// ---------------- dense update ---------------------------------------------
// out[n][j] = sum_k mean[n][k]*Wl[j][k] + b[j] + sum_k x[n][k]*Wr[j][k]
// == [mean‖x](128) @ Wc(64x128).T.  Register-tiled SGEMM:
// block: 128 nodes x 64 feats, 256 threads, thread tile 8 nodes x 4 feats.
__global__ void __launch_bounds__(256)
k_dense(const float* __restrict__ AGG, const float* __restrict__ Xin,
        const float* __restrict__ Wl, const float* __restrict__ bvec,
        const float* __restrict__ Wr, float* __restrict__ Xout, int do_relu) {
    __shared__ float As[16][132];   // [k][node], padded: stores 2-way, 16B-aligned reads
    __shared__ float Bs[16][68];    // [k][j]
    __shared__ float invs[128];
    __shared__ float bsh[64];

    int tid  = threadIdx.x;
    int base = blockIdx.x * 128;
    if (tid < 128) invs[tid] = g_INV[base + tid];
    if (tid < 64)  bsh[tid]  = __ldg(&bvec[tid]);

    int tj = tid & 15, tm = tid >> 4;
    int n0 = tm * 8, j0 = tj * 4;

    float acc[8][4];
#pragma unroll
    for (int i = 0; i < 8; ++i)
#pragma unroll
        for (int j = 0; j < 4; ++j) acc[i][j] = 0.0f;

    for (int kc = 0; kc < 8; ++kc) {
        int kc0 = kc * 16;
        __syncthreads();
        // stage A (2048 elems): k<64 -> mean = AGG*inv ; k>=64 -> Xin
#pragma unroll
        for (int r = 0; r < 8; ++r) {
            int idx = tid + r * 256;
            int kk = idx & 15, nl = idx >> 4;
            size_t g = (size_t)(base + nl) * H;
            float v;
            if (kc0 < 64) v = AGG[g + kc0 + kk] * invs[nl];
            else          v = Xin[g + kc0 - 64 + kk];
            As[kk][nl] = v;
        }
        // stage B (1024 elems)
#pragma unroll
        for (int r = 0; r < 4; ++r) {
            int idx = tid + r * 256;
            int kk = idx & 15, j = idx >> 4;
            float w = (kc0 < 64) ? __ldg(&Wl[j * 64 + kc0 + kk])
                                 : __ldg(&Wr[j * 64 + kc0 - 64 + kk]);
            Bs[kk][j] = w;
        }
        __syncthreads();
#pragma unroll
        for (int k = 0; k < 16; ++k) {
            float4 b4 = *(const float4*)&Bs[k][j0];
            float4 a0 = *(const float4*)&As[k][n0];
            float4 a1 = *(const float4*)&As[k][n0 + 4];
            float a[8] = {a0.x, a0.y, a0.z, a0.w, a1.x, a1.y, a1.z, a1.w};
            float bb[4] = {b4.x, b4.y, b4.z, b4.w};
#pragma unroll
            for (int i = 0; i < 8; ++i)
#pragma unroll
                for (int j = 0; j < 4; ++j)
                    acc[i][j] += a[i] * bb[j];
        }
    }
    // epilogue
#pragma unroll
    for (int i = 0; i < 8; ++i) {
        size_t g = (size_t)(base + n0 + i) * H + j0;
        float4 o;
        o.x = acc[i][0] + bsh[j0 + 0];
        o.y = acc[i][1] + bsh[j0 + 1];
        o.z = acc[i][2] + bsh[j0 + 2];
        o.w = acc[i][3] + bsh[j0 + 3];
        if (do_relu) {
            o.x = fmaxf(o.x, 0.0f); o.y = fmaxf(o.y, 0.0f);
            o.z = fmaxf(o.z, 0.0f); o.w = fmaxf(o.w, 0.0f);
        }
        *(float4*)&Xout[g] = o;
    }
}

// ---------------- scoring ---------------------------------------------------
// out[e] = dot(X[u[e]], X[NU + m[e]]); 16 threads per edge, shuffle reduce
__global__ void k_score(const float* __restrict__ X,
                        const void* __restrict__ eli,
                        float* __restrict__ out, int EL) {
    int t = blockIdx.x * blockDim.x + threadIdx.x;
    if (t >= EL * 16) return;
    int e = t >> 4, c = t & 15;
    int f = g_flag32[0];
    int u = get_idx(eli, e, f);
    int m = get_idx(eli, EL + e, f);
    const float4* X4 = (const float4*)X;
    float4 a = __ldg(&X4[(size_t)u * 16 + c]);
    float4 b = __ldg(&X4[(size_t)(NU + m) * 16 + c]);
    float p = a.x * b.x + a.y * b.y + a.z * b.z + a.w * b.w;
    p += __shfl_xor_sync(0xffffffffu, p, 8);
    p += __shfl_xor_sync(0xffffffffu, p, 4);
    p += __shfl_xor_sync(0xffffffffu, p, 2);
    p += __shfl_xor_sync(0xffffffffu, p, 1);
    if (c == 0) out[e] = p;
}

// ---------------- launch ----------------------------------------------------
extern "C" void kernel_launch(void* const* d_in, const int* in_sizes, int n_in,
                              void* d_out, int out_size) {
    const float* movie_x   = (const float*)d_in[0];
    const float* lin_W     = (const float*)d_in[3];
    const float* lin_b     = (const float*)d_in[4];
    const float* movie_emb = (const float*)d_in[2];
    const float* W1l = (const float*)d_in[5];
    const float* b1  = (const float*)d_in[6];
    const float* W1r = (const float*)d_in[7];
    const float* W2l = (const float*)d_in[8];
    const float* b2  = (const float*)d_in[9];
    const float* W2r = (const float*)d_in[10];
    const void*  ei  = d_in[11];
    const void*  eli = d_in[12];
    int E  = in_sizes[11] / 2;
    int EL = in_sizes[12] / 2;

    void *pX0, *pX1, *pAGG, *pDEG;
    cudaGetSymbolAddress(&pX0, g_X0);
    cudaGetSymbolAddress(&pX1, g_X1);
    cudaGetSymbolAddress(&pAGG, g_AGG);
    cudaGetSymbolAddress(&pDEG, g_DEG);

    cudaMemsetAsync(pAGG, 0, (size_t)NP * H * sizeof(float), 0);
    cudaMemsetAsync(pDEG, 0, (size_t)NP * sizeof(float), 0);

    k_zero_flag<<<1, 1>>>();
    k_detect<<<4, 256>>>((const long long*)ei, 1024);

    // node features
    cudaMemcpyAsync(pX0, d_in[1], (size_t)NU * H * sizeof(float),
                    cudaMemcpyDeviceToDevice, 0);
    k_init_movie<<<(NM * H + 255) / 256, 256>>>(movie_x, lin_W, lin_b,
                                                movie_emb, (float*)pX0);

    // degree (same for both layers)
    k_deg<<<(E + 255) / 256, 256>>>(ei, E);
    k_inv<<<(NP + 255) / 256, 256>>>();

    // layer 1
    k_scatter<<<(E * 16 + 255) / 256, 256>>>((const float4*)pX0, ei, E);
    k_dense<<<NP / 128, 256>>>((const float*)pAGG, (const float*)pX0,
                               W1l, b1, W1r, (float*)pX1, 1);
    // layer 2
    cudaMemsetAsync(pAGG, 0, (size_t)NP * H * sizeof(float), 0);
    k_scatter<<<(E * 16 + 255) / 256, 256>>>((const float4*)pX1, ei, E);
    k_dense<<<NP / 128, 256>>>((const float*)pAGG, (const float*)pX1,
                               W2l, b2, W2r, (float*)pX0, 0);

    // scoring
    k_score<<<(EL * 16 + 255) / 256, 256>>>((const float*)pX0, eli,
                                            (float*)d_out, EL);
}

// round 3
// speedup vs baseline: 1.1367x; 1.1367x over previous
#include <cuda_runtime.h>
#include <cstdint>

#define NU 200000
#define NM 80000
#define NN 280000            // real nodes
#define NP 280064            // padded to 2188*128
#define H  64

// ---------------- scratch (device globals; no allocation allowed) ----------
__device__ float g_X0[(size_t)NP * H];   // node features layer-in / final out
__device__ float g_X1[(size_t)NP * H];   // layer-1 output
__device__ float g_AGG[(size_t)NP * H];  // scatter accumulator
__device__ float g_DEG[NP];
__device__ float g_INV[NP];
__device__ int   g_flag32[1];            // 1 => indices are int32, 0 => int64

// ---------------- index dtype detection ------------------------------------
__global__ void k_zero_flag() { g_flag32[0] = 0; }

__global__ void k_detect(const long long* __restrict__ ei, int ncheck) {
    int i = blockIdx.x * blockDim.x + threadIdx.x;
    if (i < ncheck) {
        long long v = ei[i];
        if (v < 0 || v >= (long long)NN) atomicOr(g_flag32, 1);
    }
}

__device__ __forceinline__ int get_idx(const void* ei, int pos, int f32) {
    if (f32) return ((const int*)ei)[pos];
    return (int)((const long long*)ei)[pos];
}

// ---------------- node init -------------------------------------------------
__global__ void k_init_movie(const float* __restrict__ movie_x,
                             const float* __restrict__ lin_W,
                             const float* __restrict__ lin_b,
                             const float* __restrict__ movie_emb,
                             float* __restrict__ X0) {
    int t = blockIdx.x * blockDim.x + threadIdx.x;
    if (t >= NM * H) return;
    int m = t >> 6, j = t & 63;
    float acc = __ldg(&lin_b[j]);
#pragma unroll
    for (int k = 0; k < 20; ++k)
        acc += __ldg(&movie_x[m * 20 + k]) * __ldg(&lin_W[j * 20 + k]);
    X0[(size_t)(NU + m) * H + j] = acc + __ldg(&movie_emb[t]);
}

// ---------------- degree / inverse ------------------------------------------
__global__ void k_deg(const void* __restrict__ ei, int E) {
    int e = blockIdx.x * blockDim.x + threadIdx.x;
    if (e >= E) return;
    int f = g_flag32[0];
    int dst = get_idx(ei, E + e, f);
    atomicAdd(&g_DEG[dst], 1.0f);
}

__global__ void k_inv() {
    int i = blockIdx.x * blockDim.x + threadIdx.x;
    if (i < NP) g_INV[i] = 1.0f / fmaxf(g_DEG[i], 1.0f);
}

// ---------------- scatter: AGG[dst] += X[src] -------------------------------
__global__ void k_scatter(const float4* __restrict__ X,
                          const void* __restrict__ ei, int E) {
    int t = blockIdx.x * blockDim.x + threadIdx.x;
    if (t >= E * 16) return;
    int e = t >> 4, c = t & 15;
    int f = g_flag32[0];
    int src = get_idx(ei, e, f);
    int dst = get_idx(ei, E + e, f);
    float4 v = __ldg(&X[(size_t)src * 16 + c]);
    float* p = &g_AGG[(size_t)dst * H + c * 4];
    asm volatile("red.global.add.v4.f32 [%0], {%1,%2,%3,%4};"
                 :: "l"(p), "f"(v.x), "f"(v.y), "f"(v.z), "f"(v.w)
                 : "memory");
}

// ---------------- tf32 helpers ----------------------------------------------
__device__ __forceinline__ uint32_t f2tf32(float x) {
    uint32_t r;
    asm("cvt.rna.tf32.f32 %0, %1;" : "=r"(r) : "f"(x));
    return r;
}

// ---------------- dense update via tensor cores ------------------------------
// out[n][j] = sum_k mean[n][k]*Wl[j][k] + b[j] + sum_k x[n][k]*Wr[j][k]
//           = [mean‖x](NP x 128) @ Wc(128 x 64)   (Wc[k][j])
// Block: 128 nodes, 8 warps; warp w owns 16 nodes, full 64 cols.
// mma.m16n8k8.tf32: 16 K-steps (8 mean + 8 x), 8 n-frags per step.
// Bs row pad = 72 floats => B-frag LDS bank = (8k + j) mod 32, conflict-free.
__global__ void __launch_bounds__(256)
k_dense_mma(const float* __restrict__ AGG, const float* __restrict__ Xin,
            const float* __restrict__ Wl, const float* __restrict__ bvec,
            const float* __restrict__ Wr, float* __restrict__ Xout,
            int do_relu) {
    __shared__ uint32_t Bs[128][72];
    __shared__ float invs[128];
    __shared__ float bsh[64];

    int tid  = threadIdx.x;
    int base = blockIdx.x * 128;

    // stage Wc as tf32:  Bs[k][j] = (k<64 ? Wl[j][k] : Wr[j][k-64])
    for (int i = tid; i < 128 * 64; i += 256) {
        int k = i & 127, j = i >> 7;
        float w = (k < 64) ? __ldg(&Wl[j * 64 + k]) : __ldg(&Wr[j * 64 + k - 64]);
        Bs[k][j] = f2tf32(w);
    }
    if (tid < 128) invs[tid] = g_INV[base + tid];
    if (tid < 64)  bsh[tid]  = __ldg(&bvec[tid]);
    __syncthreads();

    int warp = tid >> 5, lane = tid & 31;
    int r = lane >> 2, c = lane & 3;
    int row0 = base + warp * 16 + r;        // rows row0, row0+8
    float iv0 = invs[warp * 16 + r];
    float iv1 = invs[warp * 16 + r + 8];

    float acc[8][4];
#pragma unroll
    for (int nf = 0; nf < 8; ++nf)
#pragma unroll
        for (int i = 0; i < 4; ++i) acc[nf][i] = 0.0f;

    const float* A0 = AGG + row0 * 64;
    const float* A1 = AGG + (row0 + 8) * 64;
    const float* X0p = Xin + row0 * 64;
    const float* X1p = Xin + (row0 + 8) * 64;

#pragma unroll
    for (int ks = 0; ks < 16; ++ks) {
        int k0 = ks * 8;
        uint32_t a0, a1, a2, a3;
        if (ks < 8) {
            a0 = f2tf32(__ldg(&A0[k0 + c])     * iv0);
            a1 = f2tf32(__ldg(&A1[k0 + c])     * iv1);
            a2 = f2tf32(__ldg(&A0[k0 + c + 4]) * iv0);
            a3 = f2tf32(__ldg(&A1[k0 + c + 4]) * iv1);
        } else {
            int kk = k0 - 64;
            a0 = f2tf32(__ldg(&X0p[kk + c]));
            a1 = f2tf32(__ldg(&X1p[kk + c]));
            a2 = f2tf32(__ldg(&X0p[kk + c + 4]));
            a3 = f2tf32(__ldg(&X1p[kk + c + 4]));
        }
#pragma unroll
        for (int nf = 0; nf < 8; ++nf) {
            uint32_t b0 = Bs[k0 + c][8 * nf + r];
            uint32_t b1 = Bs[k0 + c + 4][8 * nf + r];
            asm volatile(
                "mma.sync.aligned.m16n8k8.row.col.f32.tf32.tf32.f32 "
                "{%0,%1,%2,%3}, {%4,%5,%6,%7}, {%8,%9}, {%0,%1,%2,%3};"
                : "+f"(acc[nf][0]), "+f"(acc[nf][1]),
                  "+f"(acc[nf][2]), "+f"(acc[nf][3])
                : "r"(a0), "r"(a1), "r"(a2), "r"(a3), "r"(b0), "r"(b1));
        }
    }

    // epilogue: c0,c1 -> (row0, col..col+1); c2,c3 -> (row0+8, ...)
#pragma unroll
    for (int nf = 0; nf < 8; ++nf) {
        int col = 8 * nf + 2 * c;
        float o0 = acc[nf][0] + bsh[col];
        float o1 = acc[nf][1] + bsh[col + 1];
        float o2 = acc[nf][2] + bsh[col];
        float o3 = acc[nf][3] + bsh[col + 1];
        if (do_relu) {
            o0 = fmaxf(o0, 0.0f); o1 = fmaxf(o1, 0.0f);
            o2 = fmaxf(o2, 0.0f); o3 = fmaxf(o3, 0.0f);
        }
        *(float2*)&Xout[row0 * 64 + col]       = make_float2(o0, o1);
        *(float2*)&Xout[(row0 + 8) * 64 + col] = make_float2(o2, o3);
    }
}

// ---------------- scoring ---------------------------------------------------
__global__ void k_score(const float* __restrict__ X,
                        const void* __restrict__ eli,
                        float* __restrict__ out, int EL) {
    int t = blockIdx.x * blockDim.x + threadIdx.x;
    if (t >= EL * 16) return;
    int e = t >> 4, c = t & 15;
    int f = g_flag32[0];
    int u = get_idx(eli, e, f);
    int m = get_idx(eli, EL + e, f);
    const float4* X4 = (const float4*)X;
    float4 a = __ldg(&X4[(size_t)u * 16 + c]);
    float4 b = __ldg(&X4[(size_t)(NU + m) * 16 + c]);
    float p = a.x * b.x + a.y * b.y + a.z * b.z + a.w * b.w;
    p += __shfl_xor_sync(0xffffffffu, p, 8);
    p += __shfl_xor_sync(0xffffffffu, p, 4);
    p += __shfl_xor_sync(0xffffffffu, p, 2);
    p += __shfl_xor_sync(0xffffffffu, p, 1);
    if (c == 0) out[e] = p;
}

// ---------------- launch ----------------------------------------------------
extern "C" void kernel_launch(void* const* d_in, const int* in_sizes, int n_in,
                              void* d_out, int out_size) {
    const float* movie_x   = (const float*)d_in[0];
    const float* lin_W     = (const float*)d_in[3];
    const float* lin_b     = (const float*)d_in[4];
    const float* movie_emb = (const float*)d_in[2];
    const float* W1l = (const float*)d_in[5];
    const float* b1  = (const float*)d_in[6];
    const float* W1r = (const float*)d_in[7];
    const float* W2l = (const float*)d_in[8];
    const float* b2  = (const float*)d_in[9];
    const float* W2r = (const float*)d_in[10];
    const void*  ei  = d_in[11];
    const void*  eli = d_in[12];
    int E  = in_sizes[11] / 2;
    int EL = in_sizes[12] / 2;

    void *pX0, *pX1, *pAGG, *pDEG;
    cudaGetSymbolAddress(&pX0, g_X0);
    cudaGetSymbolAddress(&pX1, g_X1);
    cudaGetSymbolAddress(&pAGG, g_AGG);
    cudaGetSymbolAddress(&pDEG, g_DEG);

    cudaMemsetAsync(pAGG, 0, (size_t)NP * H * sizeof(float), 0);
    cudaMemsetAsync(pDEG, 0, (size_t)NP * sizeof(float), 0);

    k_zero_flag<<<1, 1>>>();
    k_detect<<<4, 256>>>((const long long*)ei, 1024);

    // node features
    cudaMemcpyAsync(pX0, d_in[1], (size_t)NU * H * sizeof(float),
                    cudaMemcpyDeviceToDevice, 0);
    k_init_movie<<<(NM * H + 255) / 256, 256>>>(movie_x, lin_W, lin_b,
                                                movie_emb, (float*)pX0);

    // degree (same for both layers)
    k_deg<<<(E + 255) / 256, 256>>>(ei, E);
    k_inv<<<(NP + 255) / 256, 256>>>();

    // layer 1
    k_scatter<<<(E * 16 + 255) / 256, 256>>>((const float4*)pX0, ei, E);
    k_dense_mma<<<NP / 128, 256>>>((const float*)pAGG, (const float*)pX0,
                                   W1l, b1, W1r, (float*)pX1, 1);
    // layer 2
    cudaMemsetAsync(pAGG, 0, (size_t)NP * H * sizeof(float), 0);
    k_scatter<<<(E * 16 + 255) / 256, 256>>>((const float4*)pX1, ei, E);
    k_dense_mma<<<NP / 128, 256>>>((const float*)pAGG, (const float*)pX1,
                                   W2l, b2, W2r, (float*)pX0, 0);

    // scoring
    k_score<<<(EL * 16 + 255) / 256, 256>>>((const float*)pX0, eli,
                                            (float*)d_out, EL);
}